// round 1
// baseline (speedup 1.0000x reference)
#include <cuda_runtime.h>

#define NN 64
#define TT 512
#define VV 25
#define CI 3
#define CH 64
#define FF 25
#define G4 100   // 4*FF

// Scratch (device globals: allocation-free per harness rules)
__device__ float g_zx[(size_t)NN * VV * TT * G4];   // [n][v][t][g]  328 MB
__device__ float g_f1[(size_t)NN * TT * VV * FF];   // [n][t][v][f]   82 MB

__device__ __forceinline__ float hsig(float x) {
    return fminf(fmaxf(0.2f * x + 0.5f, 0.0f), 1.0f);
}

// ---------------------------------------------------------------------------
// Kernel A: zx[n,v,t,:] = relu(x[n,t,v,:] @ Wc + bc) @ Wl + bl
// grid = N*T blocks, 256 threads. Register-blocked 4 g-outputs per thread.
// ---------------------------------------------------------------------------
__global__ void __launch_bounds__(256) zx_kernel(
    const float* __restrict__ x,   // (N,T,V,CI)
    const float* __restrict__ Wc,  // (CI,CH)
    const float* __restrict__ bc,  // (CH)
    const float* __restrict__ Wl,  // (CH,G4)
    const float* __restrict__ bl)  // (G4)
{
    const int nt = blockIdx.x;           // n*T + t
    const int n = nt / TT, t = nt % TT;
    const int tid = threadIdx.x;

    __shared__ float xs[VV * CI];
    __shared__ __align__(16) float x1s[VV * CH];

    if (tid < VV * CI) xs[tid] = x[(size_t)nt * (VV * CI) + tid];
    __syncthreads();

    // x1 = relu(x @ Wc + bc), 25x64
    for (int i = tid; i < VV * CH; i += 256) {
        int v = i / CH, d = i % CH;
        float a = bc[d];
        a += xs[v * 3 + 0] * Wc[0 * CH + d];
        a += xs[v * 3 + 1] * Wc[1 * CH + d];
        a += xs[v * 3 + 2] * Wc[2 * CH + d];
        x1s[i] = fmaxf(a, 0.0f);
    }
    __syncthreads();

    // zx = x1 @ Wl + bl, 25x100, 4 outputs per thread via float4
    const float4* Wl4 = reinterpret_cast<const float4*>(Wl);
    const float4* bl4 = reinterpret_cast<const float4*>(bl);
    for (int p = tid; p < VV * (G4 / 4); p += 256) {
        int v = p / (G4 / 4), q = p % (G4 / 4);
        float4 a = bl4[q];
        const float* xr = &x1s[v * CH];
        #pragma unroll 16
        for (int c = 0; c < CH; c++) {
            float xv = xr[c];
            float4 w = Wl4[c * (G4 / 4) + q];
            a.x += xv * w.x; a.y += xv * w.y;
            a.z += xv * w.z; a.w += xv * w.w;
        }
        float4* zrow = reinterpret_cast<float4*>(
            &g_zx[(((size_t)n * VV + v) * TT + t) * G4]);
        zrow[q] = a;
    }
}

// ---------------------------------------------------------------------------
// Kernel B: per-(n,v) LSTM scan over T. grid = N*V blocks, 128 threads.
// Thread g (0..99) owns gate column g; threads 0..24 own state (c in reg).
// ---------------------------------------------------------------------------
__global__ void __launch_bounds__(128) lstm_kernel(
    const float* __restrict__ U)   // (FF, G4)
{
    const int nv = blockIdx.x;          // n*V + v
    const int n = nv / VV, v = nv % VV;
    const int tid = threadIdx.x;

    __shared__ float hs[FF];
    __shared__ float act[G4];

    float c = 0.0f;
    if (tid < FF) hs[tid] = 0.0f;
    __syncthreads();

    const float* zp = &g_zx[(size_t)nv * TT * G4];
    const size_t f1b = ((size_t)n * TT) * (VV * FF) + (size_t)v * FF;

    float z = (tid < G4) ? zp[tid] : 0.0f;

    for (int t = 0; t < TT; t++) {
        // prefetch next step's z
        float zn = 0.0f;
        if (t + 1 < TT && tid < G4) zn = zp[(size_t)(t + 1) * G4 + tid];

        if (tid < G4) {
            float a = z;
            #pragma unroll
            for (int f = 0; f < FF; f++) a += hs[f] * U[f * G4 + tid];
            // Keras order: i[0:25], f[25:50], g[50:75], o[75:100]
            act[tid] = (tid >= 2 * FF && tid < 3 * FF) ? tanhf(a) : hsig(a);
        }
        __syncthreads();
        if (tid < FF) {
            c = act[FF + tid] * c + act[tid] * act[2 * FF + tid];
            float h = act[3 * FF + tid] * tanhf(c);
            hs[tid] = h;
            g_f1[f1b + (size_t)t * (VV * FF) + tid] = h;
        }
        __syncthreads();
        z = zn;
    }
}

// ---------------------------------------------------------------------------
// Kernel C: coefs = softmax(leaky_relu(f1)+bias, axis=-1); out = coefs @ x1
// grid = N*T blocks, 256 threads. x1 recomputed (cheap) to skip 210MB scratch.
// ---------------------------------------------------------------------------
__global__ void __launch_bounds__(256) attn_kernel(
    const float* __restrict__ x,    // (N,T,V,CI)
    const float* __restrict__ Wc,   // (CI,CH)
    const float* __restrict__ bc,   // (CH)
    const float* __restrict__ bias, // (V,V)
    float* __restrict__ out)        // (N,T,V,CH)
{
    const int nt = blockIdx.x;
    const int tid = threadIdx.x;

    __shared__ float xs[VV * CI];
    __shared__ __align__(16) float x1s[VV * CH];
    __shared__ float ft[VV * FF];
    __shared__ float cf[VV][FF];

    if (tid < VV * CI) xs[tid] = x[(size_t)nt * (VV * CI) + tid];
    for (int i = tid; i < VV * FF; i += 256)
        ft[i] = g_f1[(size_t)nt * (VV * FF) + i];
    __syncthreads();

    // recompute x1 = relu(x @ Wc + bc)
    for (int i = tid; i < VV * CH; i += 256) {
        int v = i / CH, d = i % CH;
        float a = bc[d];
        a += xs[v * 3 + 0] * Wc[0 * CH + d];
        a += xs[v * 3 + 1] * Wc[1 * CH + d];
        a += xs[v * 3 + 2] * Wc[2 * CH + d];
        x1s[i] = fmaxf(a, 0.0f);
    }

    // softmax rows: one thread per row v
    if (tid < VV) {
        float e[FF];
        float mx = -1e30f;
        #pragma unroll
        for (int w = 0; w < FF; w++) {
            float f = ft[tid * FF + w];
            f = (f > 0.0f) ? f : 0.2f * f;      // leaky_relu alpha=0.2
            f += bias[tid * VV + w];
            e[w] = f;
            mx = fmaxf(mx, f);
        }
        float s = 0.0f;
        #pragma unroll
        for (int w = 0; w < FF; w++) { float ev = __expf(e[w] - mx); e[w] = ev; s += ev; }
        float inv = 1.0f / s;
        #pragma unroll
        for (int w = 0; w < FF; w++) cf[tid][w] = e[w] * inv;
    }
    __syncthreads();

    // out[v,d] = sum_w cf[v][w] * x1[w][d]; 4 d-outputs per thread
    const float4* xq = reinterpret_cast<const float4*>(x1s);
    float4* outq = reinterpret_cast<float4*>(out) + (size_t)nt * (VV * CH / 4);
    for (int p = tid; p < VV * (CH / 4); p += 256) {
        int v = p / (CH / 4), dq = p % (CH / 4);
        float4 a = make_float4(0.f, 0.f, 0.f, 0.f);
        #pragma unroll
        for (int w = 0; w < FF; w++) {
            float cv = cf[v][w];
            float4 xv = xq[w * (CH / 4) + dq];
            a.x += cv * xv.x; a.y += cv * xv.y;
            a.z += cv * xv.z; a.w += cv * xv.w;
        }
        outq[p] = a;
    }
}

// ---------------------------------------------------------------------------
extern "C" void kernel_launch(void* const* d_in, const int* in_sizes, int n_in,
                              void* d_out, int out_size) {
    const float* x    = (const float*)d_in[0];  // (N,T,V,CI)
    const float* Wc   = (const float*)d_in[1];  // (CI,CH)
    const float* bc   = (const float*)d_in[2];  // (CH)
    const float* Wl   = (const float*)d_in[3];  // (CH,4F)
    const float* U    = (const float*)d_in[4];  // (F,4F)
    const float* bl   = (const float*)d_in[5];  // (4F)
    const float* bias = (const float*)d_in[6];  // (V,V)
    float* out = (float*)d_out;

    zx_kernel<<<NN * TT, 256>>>(x, Wc, bc, Wl, bl);
    lstm_kernel<<<NN * VV, 128>>>(U);
    attn_kernel<<<NN * TT, 256>>>(x, Wc, bc, bias, out);
}

// round 2
// speedup vs baseline: 1.8753x; 1.8753x over previous
#include <cuda_runtime.h>

#define NN 64
#define TT 512
#define VV 25
#define CI 3
#define CH 64
#define FF 25
#define G4 100   // 4*FF

// Scratch (device globals: allocation-free per harness rules)
__device__ float g_zx[(size_t)NN * VV * TT * G4];   // [n][v][t][g]
__device__ float g_f1[(size_t)NN * TT * VV * FF];   // [n][t][v][f]

typedef unsigned long long ull;

__device__ __forceinline__ ull pack2(float a, float b) {
    ull r;
    asm("mov.b64 %0, {%1,%2};" : "=l"(r) : "r"(__float_as_uint(a)), "r"(__float_as_uint(b)));
    return r;
}
__device__ __forceinline__ void unpack2(ull p, float& a, float& b) {
    unsigned int x, y;
    asm("mov.b64 {%0,%1}, %2;" : "=r"(x), "=r"(y) : "l"(p));
    a = __uint_as_float(x); b = __uint_as_float(y);
}
__device__ __forceinline__ ull fma2(ull a, ull b, ull c) {
    ull d;
    asm("fma.rn.f32x2 %0, %1, %2, %3;" : "=l"(d) : "l"(a), "l"(b), "l"(c));
    return d;
}
__device__ __forceinline__ float hsig(float x) {
    return fminf(fmaxf(0.2f * x + 0.5f, 0.0f), 1.0f);
}
__device__ __forceinline__ float tanh_fast(float x) {
    x = fminf(fmaxf(x, -9.0f), 9.0f);
    float e = __expf(2.0f * x);
    return __fdividef(e - 1.0f, e + 1.0f);
}

// ---------------------------------------------------------------------------
// Kernel A: zx[n,v,t,:] = relu(x[n,t,v,:] @ Wc + bc) @ Wl + bl
// 128 threads/block, 1 (n,t) per block. Wl staged in SMEM.
// Thread tile: 5 v-rows x 4 g-cols, f32x2 accumulators.
// ---------------------------------------------------------------------------
__global__ void __launch_bounds__(128) zx_kernel(
    const float* __restrict__ x,   // (N,T,V,CI)
    const float* __restrict__ Wc,  // (CI,CH)
    const float* __restrict__ bc,  // (CH)
    const float* __restrict__ Wl,  // (CH,G4)
    const float* __restrict__ bl)  // (G4)
{
    const int nt = blockIdx.x;
    const int n = nt / TT, t = nt % TT;
    const int tid = threadIdx.x;

    __shared__ __align__(16) float Wls[CH * G4];     // 25.6 KB
    __shared__ float x1s[VV * 65];                   // padded stride 65
    __shared__ float xs[VV * CI];
    __shared__ __align__(16) float bls[G4];

    // stage Wl, bl, x
    for (int i = tid; i < CH * G4 / 4; i += 128)
        reinterpret_cast<float4*>(Wls)[i] = reinterpret_cast<const float4*>(Wl)[i];
    if (tid < G4) bls[tid] = bl[tid];
    if (tid < VV * CI) xs[tid] = x[(size_t)nt * (VV * CI) + tid];
    __syncthreads();

    // x1 = relu(x @ Wc + bc)
    for (int i = tid; i < VV * CH; i += 128) {
        int v = i >> 6, d = i & 63;
        float a = bc[d];
        a += xs[v * 3 + 0] * Wc[0 * CH + d];
        a += xs[v * 3 + 1] * Wc[1 * CH + d];
        a += xs[v * 3 + 2] * Wc[2 * CH + d];
        x1s[v * 65 + d] = fmaxf(a, 0.0f);
    }
    __syncthreads();

    if (tid < 125) {
        const int q = tid % 25;       // quad index (4 g-cols)
        const int vg = tid / 25;      // v-group (5 rows)

        ull acc[10];                  // [i][half]
        {
            float4 b4 = *reinterpret_cast<const float4*>(&bls[4 * q]);
            #pragma unroll
            for (int i = 0; i < 5; i++) {
                acc[2 * i + 0] = pack2(b4.x, b4.y);
                acc[2 * i + 1] = pack2(b4.z, b4.w);
            }
        }
        #pragma unroll 8
        for (int c = 0; c < CH; c++) {
            float4 w = *reinterpret_cast<const float4*>(&Wls[c * G4 + 4 * q]);
            ull wlo = pack2(w.x, w.y);
            ull whi = pack2(w.z, w.w);
            #pragma unroll
            for (int i = 0; i < 5; i++) {
                float xv = x1s[(vg * 5 + i) * 65 + c];
                ull xx = pack2(xv, xv);
                acc[2 * i + 0] = fma2(xx, wlo, acc[2 * i + 0]);
                acc[2 * i + 1] = fma2(xx, whi, acc[2 * i + 1]);
            }
        }
        #pragma unroll
        for (int i = 0; i < 5; i++) {
            int v = vg * 5 + i;
            float4 r;
            unpack2(acc[2 * i + 0], r.x, r.y);
            unpack2(acc[2 * i + 1], r.z, r.w);
            *reinterpret_cast<float4*>(
                &g_zx[(((size_t)n * VV + v) * TT + t) * G4 + 4 * q]) = r;
        }
    }
}

// ---------------------------------------------------------------------------
// Kernel B: warp-per-(n,v) LSTM scan. U in registers (f32x2 packed),
// h broadcast via shfl, no smem / no barriers. 4 warps per block.
// ---------------------------------------------------------------------------
__global__ void __launch_bounds__(128) lstm_kernel(
    const float* __restrict__ U)   // (FF, G4)
{
    const int lane = threadIdx.x & 31;
    const int warp = threadIdx.x >> 5;
    const int nv = blockIdx.x * 4 + warp;
    const int n = nv / VV, v = nv % VV;
    const int j = (lane < FF) ? lane : 0;
    const bool act = (lane < FF);

    // U columns for unit j, packed (i,f) and (g,o)
    ull u_if[FF], u_go[FF];
    #pragma unroll
    for (int f = 0; f < FF; f++) {
        u_if[f] = pack2(U[f * G4 + j],          U[f * G4 + FF + j]);
        u_go[f] = pack2(U[f * G4 + 2 * FF + j], U[f * G4 + 3 * FF + j]);
    }

    const float* zp = g_zx + (size_t)nv * TT * G4;
    float* f1p = g_f1 + ((size_t)n * TT) * (VV * FF) + (size_t)v * FF + j;

    float h = 0.0f, c = 0.0f;
    // 2-step-ahead prefetch of zx
    float c0 = zp[j], c1 = zp[FF + j], c2 = zp[2 * FF + j], c3 = zp[3 * FF + j];
    float n0 = zp[G4 + j], n1 = zp[G4 + FF + j],
          n2 = zp[G4 + 2 * FF + j], n3 = zp[G4 + 3 * FF + j];

    for (int t = 0; t < TT; t++) {
        float p0 = 0.f, p1 = 0.f, p2 = 0.f, p3 = 0.f;
        if (t + 2 < TT) {
            const float* q = zp + (size_t)(t + 2) * G4;
            p0 = q[j]; p1 = q[FF + j]; p2 = q[2 * FF + j]; p3 = q[3 * FF + j];
        }

        ull acc_if = pack2(c0, c1);
        ull acc_go = pack2(c2, c3);
        #pragma unroll
        for (int f = 0; f < FF; f++) {
            float hb = __shfl_sync(0xffffffffu, h, f);
            ull hh = pack2(hb, hb);
            acc_if = fma2(hh, u_if[f], acc_if);
            acc_go = fma2(hh, u_go[f], acc_go);
        }
        float gi, gf, gg, go;
        unpack2(acc_if, gi, gf);
        unpack2(acc_go, gg, go);
        c = hsig(gf) * c + hsig(gi) * tanh_fast(gg);
        h = hsig(go) * tanh_fast(c);
        if (act) f1p[(size_t)t * (VV * FF)] = h;

        c0 = n0; c1 = n1; c2 = n2; c3 = n3;
        n0 = p0; n1 = p1; n2 = p2; n3 = p3;
    }
}

// ---------------------------------------------------------------------------
// Kernel C: coefs = softmax(leaky_relu(f1)+bias); out = coefs @ x1
// 256 threads/block; agg thread owns (v, 8 d-cols), cf row in registers.
// ---------------------------------------------------------------------------
__global__ void __launch_bounds__(256) attn_kernel(
    const float* __restrict__ x,    // (N,T,V,CI)
    const float* __restrict__ Wc,   // (CI,CH)
    const float* __restrict__ bc,   // (CH)
    const float* __restrict__ bias, // (V,V)
    float* __restrict__ out)        // (N,T,V,CH)
{
    const int nt = blockIdx.x;
    const int tid = threadIdx.x;

    __shared__ float xs[VV * CI];
    __shared__ __align__(16) float x1s[VV * 72];   // padded stride 72
    __shared__ float ft[VV * FF];
    __shared__ float cfs[VV][FF];

    if (tid < VV * CI) xs[tid] = x[(size_t)nt * (VV * CI) + tid];
    for (int i = tid; i < VV * FF; i += 256)
        ft[i] = g_f1[(size_t)nt * (VV * FF) + i];
    __syncthreads();

    // recompute x1 = relu(x @ Wc + bc)
    for (int i = tid; i < VV * CH; i += 256) {
        int v = i >> 6, d = i & 63;
        float a = bc[d];
        a += xs[v * 3 + 0] * Wc[0 * CH + d];
        a += xs[v * 3 + 1] * Wc[1 * CH + d];
        a += xs[v * 3 + 2] * Wc[2 * CH + d];
        x1s[v * 72 + d] = fmaxf(a, 0.0f);
    }

    // rowwise softmax(leaky_relu(f1) + bias)
    if (tid < VV) {
        float e[FF];
        float mx = -1e30f;
        #pragma unroll
        for (int w = 0; w < FF; w++) {
            float f = ft[tid * FF + w];
            f = (f > 0.0f) ? f : 0.2f * f;
            f += bias[tid * VV + w];
            e[w] = f;
            mx = fmaxf(mx, f);
        }
        float s = 0.0f;
        #pragma unroll
        for (int w = 0; w < FF; w++) { float ev = __expf(e[w] - mx); e[w] = ev; s += ev; }
        float inv = __fdividef(1.0f, s);
        #pragma unroll
        for (int w = 0; w < FF; w++) cfs[tid][w] = e[w] * inv;
    }
    __syncthreads();

    // out[v, d8:d8+8] = sum_w cf[v][w] * x1[w, d8:d8+8]
    if (tid < 200) {
        const int v = tid >> 3;
        const int d8 = (tid & 7) * 8;
        ull a0 = 0, a1 = 0, a2 = 0, a3 = 0;
        #pragma unroll
        for (int w = 0; w < FF; w++) {
            float cv = cfs[v][w];
            ull cc = pack2(cv, cv);
            const float4* r = reinterpret_cast<const float4*>(&x1s[w * 72 + d8]);
            float4 A = r[0], B = r[1];
            a0 = fma2(cc, pack2(A.x, A.y), a0);
            a1 = fma2(cc, pack2(A.z, A.w), a1);
            a2 = fma2(cc, pack2(B.x, B.y), a2);
            a3 = fma2(cc, pack2(B.z, B.w), a3);
        }
        float4 r0, r1;
        unpack2(a0, r0.x, r0.y); unpack2(a1, r0.z, r0.w);
        unpack2(a2, r1.x, r1.y); unpack2(a3, r1.z, r1.w);
        float4* o = reinterpret_cast<float4*>(out + (size_t)nt * (VV * CH) + v * CH + d8);
        o[0] = r0; o[1] = r1;
    }
}

// ---------------------------------------------------------------------------
extern "C" void kernel_launch(void* const* d_in, const int* in_sizes, int n_in,
                              void* d_out, int out_size) {
    const float* x    = (const float*)d_in[0];
    const float* Wc   = (const float*)d_in[1];
    const float* bc   = (const float*)d_in[2];
    const float* Wl   = (const float*)d_in[3];
    const float* U    = (const float*)d_in[4];
    const float* bl   = (const float*)d_in[5];
    const float* bias = (const float*)d_in[6];
    float* out = (float*)d_out;

    zx_kernel<<<NN * TT, 128>>>(x, Wc, bc, Wl, bl);
    lstm_kernel<<<NN * VV / 4, 128>>>(U);
    attn_kernel<<<NN * TT, 256>>>(x, Wc, bc, bias, out);
}

// round 3
// speedup vs baseline: 1.8808x; 1.0030x over previous
#include <cuda_runtime.h>

#define NN 64
#define TT 512
#define VV 25
#define CI 3
#define CH 64
#define FF 25
#define G4 100   // 4*FF
#define MROWS ((size_t)NN * TT * VV)   // 819200 rows of the flat GEMM

// Scratch (device globals: allocation-free per harness rules)
__device__ float g_zx[(size_t)NN * VV * TT * G4];   // [n][v][t][g]
__device__ float g_f1[(size_t)NN * TT * VV * FF];   // [n][t][v][f]

typedef unsigned long long ull;

__device__ __forceinline__ ull pack2(float a, float b) {
    ull r;
    asm("mov.b64 %0, {%1,%2};" : "=l"(r) : "r"(__float_as_uint(a)), "r"(__float_as_uint(b)));
    return r;
}
__device__ __forceinline__ void unpack2(ull p, float& a, float& b) {
    unsigned int x, y;
    asm("mov.b64 {%0,%1}, %2;" : "=r"(x), "=r"(y) : "l"(p));
    a = __uint_as_float(x); b = __uint_as_float(y);
}
__device__ __forceinline__ ull fma2(ull a, ull b, ull c) {
    ull d;
    asm("fma.rn.f32x2 %0, %1, %2, %3;" : "=l"(d) : "l"(a), "l"(b), "l"(c));
    return d;
}
__device__ __forceinline__ float hsig(float x) {
    return fminf(fmaxf(0.2f * x + 0.5f, 0.0f), 1.0f);
}
__device__ __forceinline__ float tanh_fast(float x) {
    x = fminf(fmaxf(x, -9.0f), 9.0f);
    float e = __expf(2.0f * x);
    return __fdividef(e - 1.0f, e + 1.0f);
}

// ---------------------------------------------------------------------------
// Kernel A: flat GEMM  zx[row, :] = relu(x[row,:3] @ Wc + bc) @ Wl + bl
// Block: 416 threads = 13 warps, 128 rows. Warp w owns g-octet 8w..8w+7
// (uniform __ldg weights). x1 stored transposed in SMEM; lane reads 4 rows
// per k via one conflict-free LDS.128. 16 FFMA2 per thread per k.
// ---------------------------------------------------------------------------
__global__ void __launch_bounds__(416, 2) zx_kernel(
    const float* __restrict__ x,   // (N*T*V, CI) flattened
    const float* __restrict__ Wc,  // (CI,CH)
    const float* __restrict__ bc,  // (CH)
    const float* __restrict__ Wl,  // (CH,G4)
    const float* __restrict__ bl)  // (G4)
{
    const int tid  = threadIdx.x;
    const int warp = tid >> 5;
    const int lane = tid & 31;
    const size_t base = (size_t)blockIdx.x * 128;

    __shared__ __align__(16) float x1T[CH * 128];   // 32 KB, [c][r]
    __shared__ float xs[128 * CI];                   // 384
    __shared__ float Wcs[CI * CH];                   // 192
    __shared__ float bcs[CH];

    // stage inputs (x rows are contiguous: row*3 + ci)
    if (tid < 384) xs[tid] = x[base * 3 + tid];
    if (tid < 192) Wcs[tid] = Wc[tid];
    if (tid < CH)  bcs[tid] = bc[tid];
    __syncthreads();

    // phase 1: x1T[c][r] = relu(x[r,:] @ Wc[:,c] + bc[c])
    for (int i = tid; i < CH * 128; i += 416) {
        int c = i >> 7, r = i & 127;
        float a = bcs[c];
        a += xs[r * 3 + 0] * Wcs[c];
        a += xs[r * 3 + 1] * Wcs[CH + c];
        a += xs[r * 3 + 2] * Wcs[2 * CH + c];
        x1T[c * 128 + r] = fmaxf(a, 0.0f);
    }
    __syncthreads();

    // phase 2: per-warp octet GEMM
    const int g0 = warp * 8;
    const bool full = (warp < 12);          // octet 12 covers g 96..99 only

    ull acc[16];                            // [row i][pair j]: g0+2j, g0+2j+1
    {
        float4 ba = __ldg(reinterpret_cast<const float4*>(&bl[g0]));
        float4 bb = full ? __ldg(reinterpret_cast<const float4*>(&bl[g0 + 4]))
                         : make_float4(0.f, 0.f, 0.f, 0.f);
        #pragma unroll
        for (int i = 0; i < 4; i++) {
            acc[i * 4 + 0] = pack2(ba.x, ba.y);
            acc[i * 4 + 1] = pack2(ba.z, ba.w);
            acc[i * 4 + 2] = pack2(bb.x, bb.y);
            acc[i * 4 + 3] = pack2(bb.z, bb.w);
        }
    }

    const int r0 = lane * 4;
    #pragma unroll 4
    for (int c = 0; c < CH; c++) {
        float4 xv = *reinterpret_cast<const float4*>(&x1T[c * 128 + r0]);
        float4 wa = __ldg(reinterpret_cast<const float4*>(&Wl[c * G4 + g0]));
        float4 wb = full ? __ldg(reinterpret_cast<const float4*>(&Wl[c * G4 + g0 + 4]))
                         : make_float4(0.f, 0.f, 0.f, 0.f);
        ull w0 = pack2(wa.x, wa.y), w1 = pack2(wa.z, wa.w);
        ull w2 = pack2(wb.x, wb.y), w3 = pack2(wb.z, wb.w);
        float xr[4] = {xv.x, xv.y, xv.z, xv.w};
        #pragma unroll
        for (int i = 0; i < 4; i++) {
            ull xx = pack2(xr[i], xr[i]);
            acc[i * 4 + 0] = fma2(xx, w0, acc[i * 4 + 0]);
            acc[i * 4 + 1] = fma2(xx, w1, acc[i * 4 + 1]);
            acc[i * 4 + 2] = fma2(xx, w2, acc[i * 4 + 2]);
            acc[i * 4 + 3] = fma2(xx, w3, acc[i * 4 + 3]);
        }
    }

    // epilogue: scatter to g_zx[n][v][t][g]
    #pragma unroll
    for (int i = 0; i < 4; i++) {
        size_t row = base + r0 + i;
        int nt = (int)(row / VV);
        int v  = (int)(row - (size_t)nt * VV);
        int n  = nt >> 9, t = nt & 511;
        float* dst = &g_zx[(((size_t)n * VV + v) * TT + t) * G4 + g0];
        float4 A, B;
        unpack2(acc[i * 4 + 0], A.x, A.y); unpack2(acc[i * 4 + 1], A.z, A.w);
        unpack2(acc[i * 4 + 2], B.x, B.y); unpack2(acc[i * 4 + 3], B.z, B.w);
        *reinterpret_cast<float4*>(dst) = A;
        if (full) *reinterpret_cast<float4*>(dst + 4) = B;
    }
}

// ---------------------------------------------------------------------------
// Kernel B: warp-per-(n,v) LSTM scan. U in registers (f32x2 packed),
// h broadcast via shfl, no smem / no barriers. 4 warps per block.
// ---------------------------------------------------------------------------
__global__ void __launch_bounds__(128) lstm_kernel(
    const float* __restrict__ U)   // (FF, G4)
{
    const int lane = threadIdx.x & 31;
    const int warp = threadIdx.x >> 5;
    const int nv = blockIdx.x * 4 + warp;
    const int n = nv / VV, v = nv % VV;
    const int j = (lane < FF) ? lane : 0;
    const bool act = (lane < FF);

    ull u_if[FF], u_go[FF];
    #pragma unroll
    for (int f = 0; f < FF; f++) {
        u_if[f] = pack2(U[f * G4 + j],          U[f * G4 + FF + j]);
        u_go[f] = pack2(U[f * G4 + 2 * FF + j], U[f * G4 + 3 * FF + j]);
    }

    const float* zp = g_zx + (size_t)nv * TT * G4;
    float* f1p = g_f1 + ((size_t)n * TT) * (VV * FF) + (size_t)v * FF + j;

    float h = 0.0f, c = 0.0f;
    float c0 = zp[j], c1 = zp[FF + j], c2 = zp[2 * FF + j], c3 = zp[3 * FF + j];
    float n0 = zp[G4 + j], n1 = zp[G4 + FF + j],
          n2 = zp[G4 + 2 * FF + j], n3 = zp[G4 + 3 * FF + j];

    for (int t = 0; t < TT; t++) {
        float p0 = 0.f, p1 = 0.f, p2 = 0.f, p3 = 0.f;
        if (t + 2 < TT) {
            const float* q = zp + (size_t)(t + 2) * G4;
            p0 = q[j]; p1 = q[FF + j]; p2 = q[2 * FF + j]; p3 = q[3 * FF + j];
        }

        ull acc_if = pack2(c0, c1);
        ull acc_go = pack2(c2, c3);
        #pragma unroll
        for (int f = 0; f < FF; f++) {
            float hb = __shfl_sync(0xffffffffu, h, f);
            ull hh = pack2(hb, hb);
            acc_if = fma2(hh, u_if[f], acc_if);
            acc_go = fma2(hh, u_go[f], acc_go);
        }
        float gi, gf, gg, go;
        unpack2(acc_if, gi, gf);
        unpack2(acc_go, gg, go);
        c = hsig(gf) * c + hsig(gi) * tanh_fast(gg);
        h = hsig(go) * tanh_fast(c);
        if (act) f1p[(size_t)t * (VV * FF)] = h;

        c0 = n0; c1 = n1; c2 = n2; c3 = n3;
        n0 = p0; n1 = p1; n2 = p2; n3 = p3;
    }
}

// ---------------------------------------------------------------------------
// Kernel C: coefs = softmax(leaky_relu(f1)+bias); out = coefs @ x1
// ---------------------------------------------------------------------------
__global__ void __launch_bounds__(256) attn_kernel(
    const float* __restrict__ x,    // (N,T,V,CI)
    const float* __restrict__ Wc,   // (CI,CH)
    const float* __restrict__ bc,   // (CH)
    const float* __restrict__ bias, // (V,V)
    float* __restrict__ out)        // (N,T,V,CH)
{
    const int nt = blockIdx.x;
    const int tid = threadIdx.x;

    __shared__ float xs[VV * CI];
    __shared__ __align__(16) float x1s[VV * 72];
    __shared__ float ft[VV * FF];
    __shared__ float cfs[VV][FF];

    if (tid < VV * CI) xs[tid] = x[(size_t)nt * (VV * CI) + tid];
    for (int i = tid; i < VV * FF; i += 256)
        ft[i] = g_f1[(size_t)nt * (VV * FF) + i];
    __syncthreads();

    for (int i = tid; i < VV * CH; i += 256) {
        int v = i >> 6, d = i & 63;
        float a = bc[d];
        a += xs[v * 3 + 0] * Wc[0 * CH + d];
        a += xs[v * 3 + 1] * Wc[1 * CH + d];
        a += xs[v * 3 + 2] * Wc[2 * CH + d];
        x1s[v * 72 + d] = fmaxf(a, 0.0f);
    }

    if (tid < VV) {
        float e[FF];
        float mx = -1e30f;
        #pragma unroll
        for (int w = 0; w < FF; w++) {
            float f = ft[tid * FF + w];
            f = (f > 0.0f) ? f : 0.2f * f;
            f += bias[tid * VV + w];
            e[w] = f;
            mx = fmaxf(mx, f);
        }
        float s = 0.0f;
        #pragma unroll
        for (int w = 0; w < FF; w++) { float ev = __expf(e[w] - mx); e[w] = ev; s += ev; }
        float inv = __fdividef(1.0f, s);
        #pragma unroll
        for (int w = 0; w < FF; w++) cfs[tid][w] = e[w] * inv;
    }
    __syncthreads();

    if (tid < 200) {
        const int v = tid >> 3;
        const int d8 = (tid & 7) * 8;
        ull a0 = 0, a1 = 0, a2 = 0, a3 = 0;
        #pragma unroll
        for (int w = 0; w < FF; w++) {
            float cv = cfs[v][w];
            ull cc = pack2(cv, cv);
            const float4* r = reinterpret_cast<const float4*>(&x1s[w * 72 + d8]);
            float4 A = r[0], B = r[1];
            a0 = fma2(cc, pack2(A.x, A.y), a0);
            a1 = fma2(cc, pack2(A.z, A.w), a1);
            a2 = fma2(cc, pack2(B.x, B.y), a2);
            a3 = fma2(cc, pack2(B.z, B.w), a3);
        }
        float4 r0, r1;
        unpack2(a0, r0.x, r0.y); unpack2(a1, r0.z, r0.w);
        unpack2(a2, r1.x, r1.y); unpack2(a3, r1.z, r1.w);
        float4* o = reinterpret_cast<float4*>(out + (size_t)nt * (VV * CH) + v * CH + d8);
        o[0] = r0; o[1] = r1;
    }
}

// ---------------------------------------------------------------------------
extern "C" void kernel_launch(void* const* d_in, const int* in_sizes, int n_in,
                              void* d_out, int out_size) {
    const float* x    = (const float*)d_in[0];
    const float* Wc   = (const float*)d_in[1];
    const float* bc   = (const float*)d_in[2];
    const float* Wl   = (const float*)d_in[3];
    const float* U    = (const float*)d_in[4];
    const float* bl   = (const float*)d_in[5];
    const float* bias = (const float*)d_in[6];
    float* out = (float*)d_out;

    zx_kernel<<<(int)(MROWS / 128), 416>>>(x, Wc, bc, Wl, bl);
    lstm_kernel<<<NN * VV / 4, 128>>>(U);
    attn_kernel<<<NN * TT, 256>>>(x, Wc, bc, bias, out);
}

// round 5
// speedup vs baseline: 1.9573x; 1.0407x over previous
#include <cuda_runtime.h>

#define NN 64
#define TT 512
#define VV 25
#define CI 3
#define CH 64
#define FF 25
#define G4 100   // 4*FF
#define MROWS ((size_t)NN * TT * VV)   // 819200

// Scratch (device globals: allocation-free per harness rules)
__device__ float g_zx[(size_t)NN * VV * TT * G4];   // [n][v][t][g]
__device__ float g_f1[(size_t)NN * TT * VV * FF];   // [n][t][v][f]

typedef unsigned long long ull;

__device__ __forceinline__ ull pack2(float a, float b) {
    ull r;
    asm("mov.b64 %0, {%1,%2};" : "=l"(r) : "r"(__float_as_uint(a)), "r"(__float_as_uint(b)));
    return r;
}
__device__ __forceinline__ void unpack2(ull p, float& a, float& b) {
    unsigned int x, y;
    asm("mov.b64 {%0,%1}, %2;" : "=r"(x), "=r"(y) : "l"(p));
    a = __uint_as_float(x); b = __uint_as_float(y);
}
__device__ __forceinline__ ull fma2(ull a, ull b, ull c) {
    ull d;
    asm("fma.rn.f32x2 %0, %1, %2, %3;" : "=l"(d) : "l"(a), "l"(b), "l"(c));
    return d;
}
__device__ __forceinline__ ull add2(ull a, ull b) {
    ull d;
    asm("add.rn.f32x2 %0, %1, %2;" : "=l"(d) : "l"(a), "l"(b));
    return d;
}
__device__ __forceinline__ float hsig(float x) {
    return fminf(fmaxf(0.2f * x + 0.5f, 0.0f), 1.0f);
}
__device__ __forceinline__ float tanh_hw(float x) {
    float y;
    asm("tanh.approx.f32 %0, %1;" : "=f"(y) : "f"(x));
    return y;
}

// ---------------------------------------------------------------------------
// Kernel A: flat GEMM  zx[row, :] = relu(x[row,:3] @ Wc + bc) @ Wl + bl
// (R3-passing version, 365us)
// ---------------------------------------------------------------------------
__global__ void __launch_bounds__(416, 2) zx_kernel(
    const float* __restrict__ x,   // (N*T*V, CI) flattened
    const float* __restrict__ Wc,  // (CI,CH)
    const float* __restrict__ bc,  // (CH)
    const float* __restrict__ Wl,  // (CH,G4)
    const float* __restrict__ bl)  // (G4)
{
    const int tid  = threadIdx.x;
    const int warp = tid >> 5;
    const int lane = tid & 31;
    const size_t base = (size_t)blockIdx.x * 128;

    __shared__ __align__(16) float x1T[CH * 128];   // 32 KB, [c][r]
    __shared__ float xs[128 * CI];
    __shared__ float Wcs[CI * CH];
    __shared__ float bcs[CH];

    if (tid < 384) xs[tid] = x[base * 3 + tid];
    if (tid < 192) Wcs[tid] = Wc[tid];
    if (tid < CH)  bcs[tid] = bc[tid];
    __syncthreads();

    for (int i = tid; i < CH * 128; i += 416) {
        int c = i >> 7, r = i & 127;
        float a = bcs[c];
        a += xs[r * 3 + 0] * Wcs[c];
        a += xs[r * 3 + 1] * Wcs[CH + c];
        a += xs[r * 3 + 2] * Wcs[2 * CH + c];
        x1T[c * 128 + r] = fmaxf(a, 0.0f);
    }
    __syncthreads();

    const int g0 = warp * 8;
    const bool full = (warp < 12);

    ull acc[16];
    {
        float4 ba = __ldg(reinterpret_cast<const float4*>(&bl[g0]));
        float4 bb = full ? __ldg(reinterpret_cast<const float4*>(&bl[g0 + 4]))
                         : make_float4(0.f, 0.f, 0.f, 0.f);
        #pragma unroll
        for (int i = 0; i < 4; i++) {
            acc[i * 4 + 0] = pack2(ba.x, ba.y);
            acc[i * 4 + 1] = pack2(ba.z, ba.w);
            acc[i * 4 + 2] = pack2(bb.x, bb.y);
            acc[i * 4 + 3] = pack2(bb.z, bb.w);
        }
    }

    const int r0 = lane * 4;
    #pragma unroll 4
    for (int c = 0; c < CH; c++) {
        float4 xv = *reinterpret_cast<const float4*>(&x1T[c * 128 + r0]);
        float4 wa = __ldg(reinterpret_cast<const float4*>(&Wl[c * G4 + g0]));
        float4 wb = full ? __ldg(reinterpret_cast<const float4*>(&Wl[c * G4 + g0 + 4]))
                         : make_float4(0.f, 0.f, 0.f, 0.f);
        ull w0 = pack2(wa.x, wa.y), w1 = pack2(wa.z, wa.w);
        ull w2 = pack2(wb.x, wb.y), w3 = pack2(wb.z, wb.w);
        float xr[4] = {xv.x, xv.y, xv.z, xv.w};
        #pragma unroll
        for (int i = 0; i < 4; i++) {
            ull xx = pack2(xr[i], xr[i]);
            acc[i * 4 + 0] = fma2(xx, w0, acc[i * 4 + 0]);
            acc[i * 4 + 1] = fma2(xx, w1, acc[i * 4 + 1]);
            acc[i * 4 + 2] = fma2(xx, w2, acc[i * 4 + 2]);
            acc[i * 4 + 3] = fma2(xx, w3, acc[i * 4 + 3]);
        }
    }

    #pragma unroll
    for (int i = 0; i < 4; i++) {
        size_t row = base + r0 + i;
        int nt = (int)(row / VV);
        int v  = (int)(row - (size_t)nt * VV);
        int n  = nt >> 9, t = nt & 511;
        float* dst = &g_zx[(((size_t)n * VV + v) * TT + t) * G4 + g0];
        float4 A, B;
        unpack2(acc[i * 4 + 0], A.x, A.y); unpack2(acc[i * 4 + 1], A.z, A.w);
        unpack2(acc[i * 4 + 2], B.x, B.y); unpack2(acc[i * 4 + 3], B.z, B.w);
        *reinterpret_cast<float4*>(dst) = A;
        if (full) *reinterpret_cast<float4*>(dst + 4) = B;
    }
}

// ---------------------------------------------------------------------------
// Kernel B: warp-per-(n,v) LSTM scan. U in registers, h via shfl.
// Split accumulator chains (2x) + MUFU tanh to cut the serial critical path.
// 64-thread blocks for SM balance (800 blocks).
// ---------------------------------------------------------------------------
__global__ void __launch_bounds__(64) lstm_kernel(
    const float* __restrict__ U)   // (FF, G4)
{
    const int lane = threadIdx.x & 31;
    const int warp = threadIdx.x >> 5;
    const int nv = blockIdx.x * 2 + warp;
    const int n = nv / VV, v = nv % VV;
    const int j = (lane < FF) ? lane : 0;
    const bool act = (lane < FF);

    ull u_if[FF], u_go[FF];
    #pragma unroll
    for (int f = 0; f < FF; f++) {
        u_if[f] = pack2(U[f * G4 + j],          U[f * G4 + FF + j]);
        u_go[f] = pack2(U[f * G4 + 2 * FF + j], U[f * G4 + 3 * FF + j]);
    }

    const float* zp = g_zx + (size_t)nv * TT * G4;
    float* f1p = g_f1 + ((size_t)n * TT) * (VV * FF) + (size_t)v * FF + j;

    float h = 0.0f, c = 0.0f;
    float c0 = zp[j], c1 = zp[FF + j], c2 = zp[2 * FF + j], c3 = zp[3 * FF + j];
    float n0 = zp[G4 + j], n1 = zp[G4 + FF + j],
          n2 = zp[G4 + 2 * FF + j], n3 = zp[G4 + 3 * FF + j];

    for (int t = 0; t < TT; t++) {
        float p0 = 0.f, p1 = 0.f, p2 = 0.f, p3 = 0.f;
        if (t + 2 < TT) {
            const float* q = zp + (size_t)(t + 2) * G4;
            p0 = q[j]; p1 = q[FF + j]; p2 = q[2 * FF + j]; p3 = q[3 * FF + j];
        }

        // two independent chains per gate pair -> halved dependent-FMA path
        ull if0 = pack2(c0, c1), if1 = 0;
        ull go0 = pack2(c2, c3), go1 = 0;
        #pragma unroll
        for (int f = 0; f < 12; f++) {
            float hb = __shfl_sync(0xffffffffu, h, f);
            ull hh = pack2(hb, hb);
            if0 = fma2(hh, u_if[f], if0);
            go0 = fma2(hh, u_go[f], go0);
        }
        #pragma unroll
        for (int f = 12; f < FF; f++) {
            float hb = __shfl_sync(0xffffffffu, h, f);
            ull hh = pack2(hb, hb);
            if1 = fma2(hh, u_if[f], if1);
            go1 = fma2(hh, u_go[f], go1);
        }
        ull acc_if = add2(if0, if1);
        ull acc_go = add2(go0, go1);

        float gi, gf, gg, go;
        unpack2(acc_if, gi, gf);
        unpack2(acc_go, gg, go);
        c = hsig(gf) * c + hsig(gi) * tanh_hw(gg);
        h = hsig(go) * tanh_hw(c);
        if (act) f1p[(size_t)t * (VV * FF)] = h;

        c0 = n0; c1 = n1; c2 = n2; c3 = n3;
        n0 = p0; n1 = p1; n2 = p2; n3 = p3;
    }
}

// ---------------------------------------------------------------------------
// Kernel C: coefs = softmax(leaky_relu(f1)+bias); out = coefs @ x1
// (R3-passing version)
// ---------------------------------------------------------------------------
__global__ void __launch_bounds__(256) attn_kernel(
    const float* __restrict__ x,
    const float* __restrict__ Wc,
    const float* __restrict__ bc,
    const float* __restrict__ bias,
    float* __restrict__ out)
{
    const int nt = blockIdx.x;
    const int tid = threadIdx.x;

    __shared__ float xs[VV * CI];
    __shared__ __align__(16) float x1s[VV * 72];
    __shared__ float ft[VV * FF];
    __shared__ float cfs[VV][FF];

    if (tid < VV * CI) xs[tid] = x[(size_t)nt * (VV * CI) + tid];
    for (int i = tid; i < VV * FF; i += 256)
        ft[i] = g_f1[(size_t)nt * (VV * FF) + i];
    __syncthreads();

    for (int i = tid; i < VV * CH; i += 256) {
        int v = i >> 6, d = i & 63;
        float a = bc[d];
        a += xs[v * 3 + 0] * Wc[0 * CH + d];
        a += xs[v * 3 + 1] * Wc[1 * CH + d];
        a += xs[v * 3 + 2] * Wc[2 * CH + d];
        x1s[v * 72 + d] = fmaxf(a, 0.0f);
    }

    if (tid < VV) {
        float e[FF];
        float mx = -1e30f;
        #pragma unroll
        for (int w = 0; w < FF; w++) {
            float f = ft[tid * FF + w];
            f = (f > 0.0f) ? f : 0.2f * f;
            f += bias[tid * VV + w];
            e[w] = f;
            mx = fmaxf(mx, f);
        }
        float s = 0.0f;
        #pragma unroll
        for (int w = 0; w < FF; w++) { float ev = __expf(e[w] - mx); e[w] = ev; s += ev; }
        float inv = __fdividef(1.0f, s);
        #pragma unroll
        for (int w = 0; w < FF; w++) cfs[tid][w] = e[w] * inv;
    }
    __syncthreads();

    if (tid < 200) {
        const int v = tid >> 3;
        const int d8 = (tid & 7) * 8;
        ull a0 = 0, a1 = 0, a2 = 0, a3 = 0;
        #pragma unroll
        for (int w = 0; w < FF; w++) {
            float cv = cfs[v][w];
            ull cc = pack2(cv, cv);
            const float4* r = reinterpret_cast<const float4*>(&x1s[w * 72 + d8]);
            float4 A = r[0], B = r[1];
            a0 = fma2(cc, pack2(A.x, A.y), a0);
            a1 = fma2(cc, pack2(A.z, A.w), a1);
            a2 = fma2(cc, pack2(B.x, B.y), a2);
            a3 = fma2(cc, pack2(B.z, B.w), a3);
        }
        float4 r0, r1;
        unpack2(a0, r0.x, r0.y); unpack2(a1, r0.z, r0.w);
        unpack2(a2, r1.x, r1.y); unpack2(a3, r1.z, r1.w);
        float4* o = reinterpret_cast<float4*>(out + (size_t)nt * (VV * CH) + v * CH + d8);
        o[0] = r0; o[1] = r1;
    }
}

// ---------------------------------------------------------------------------
extern "C" void kernel_launch(void* const* d_in, const int* in_sizes, int n_in,
                              void* d_out, int out_size) {
    const float* x    = (const float*)d_in[0];
    const float* Wc   = (const float*)d_in[1];
    const float* bc   = (const float*)d_in[2];
    const float* Wl   = (const float*)d_in[3];
    const float* U    = (const float*)d_in[4];
    const float* bl   = (const float*)d_in[5];
    const float* bias = (const float*)d_in[6];
    float* out = (float*)d_out;

    zx_kernel<<<(int)(MROWS / 128), 416>>>(x, Wc, bc, Wl, bl);
    lstm_kernel<<<NN * VV / 2, 64>>>(U);
    attn_kernel<<<NN * TT, 256>>>(x, Wc, bc, bias, out);
}

// round 6
// speedup vs baseline: 2.6500x; 1.3539x over previous
#include <cuda_runtime.h>
#include <cstdint>

#define NN 64
#define TT 512
#define VV 25
#define CI 3
#define CH 64
#define FF 25
#define G4 100   // 4*FF
#define MROWS ((size_t)NN * TT * VV)   // 819200

// Scratch (device globals: allocation-free per harness rules)
__device__ float g_zx[(size_t)NN * VV * TT * G4];   // [n][v][t][g]
__device__ float g_f1[(size_t)NN * TT * VV * FF];   // [n][t][v][f]

typedef unsigned long long ull;

__device__ __forceinline__ ull pack2(float a, float b) {
    ull r;
    asm("mov.b64 %0, {%1,%2};" : "=l"(r) : "r"(__float_as_uint(a)), "r"(__float_as_uint(b)));
    return r;
}
__device__ __forceinline__ void unpack2(ull p, float& a, float& b) {
    unsigned int x, y;
    asm("mov.b64 {%0,%1}, %2;" : "=r"(x), "=r"(y) : "l"(p));
    a = __uint_as_float(x); b = __uint_as_float(y);
}
__device__ __forceinline__ ull fma2(ull a, ull b, ull c) {
    ull d;
    asm("fma.rn.f32x2 %0, %1, %2, %3;" : "=l"(d) : "l"(a), "l"(b), "l"(c));
    return d;
}
__device__ __forceinline__ ull add2(ull a, ull b) {
    ull d;
    asm("add.rn.f32x2 %0, %1, %2;" : "=l"(d) : "l"(a), "l"(b));
    return d;
}
__device__ __forceinline__ float hsig(float x) {
    return fminf(fmaxf(0.2f * x + 0.5f, 0.0f), 1.0f);
}
__device__ __forceinline__ float tanh_hw(float x) {
    float y;
    asm("tanh.approx.f32 %0, %1;" : "=f"(y) : "f"(x));
    return y;
}
__device__ __forceinline__ uint32_t to_tf32(float x) {
    uint32_t r;
    asm("cvt.rna.tf32.f32 %0, %1;" : "=r"(r) : "f"(x));
    return r;
}
__device__ __forceinline__ void mma_tf32(float* c, const uint32_t* a, const uint32_t* b) {
    asm("mma.sync.aligned.m16n8k8.row.col.f32.tf32.tf32.f32 "
        "{%0,%1,%2,%3}, {%4,%5,%6,%7}, {%8,%9}, {%0,%1,%2,%3};"
        : "+f"(c[0]), "+f"(c[1]), "+f"(c[2]), "+f"(c[3])
        : "r"(a[0]), "r"(a[1]), "r"(a[2]), "r"(a[3]), "r"(b[0]), "r"(b[1]));
}

// ---------------------------------------------------------------------------
// Kernel A: tf32 mma.sync GEMM.  zx[row,:] = relu(x[row]@Wc+bc) @ Wl + bl
// 256 threads = 8 warps: 4 along M (32 rows each) x 2 along N (56 cols each).
// A fragments computed from the conv in-register; B via __ldg (Wl L1-hot).
// ---------------------------------------------------------------------------
__global__ void __launch_bounds__(256) zx_kernel(
    const float* __restrict__ x,   // (N*T*V, CI) flattened
    const float* __restrict__ Wc,  // (CI,CH)
    const float* __restrict__ bc,  // (CH)
    const float* __restrict__ Wl,  // (CH,G4)
    const float* __restrict__ bl)  // (G4)
{
    const int tid  = threadIdx.x;
    const int warp = tid >> 5;
    const int lane = tid & 31;
    const size_t base = (size_t)blockIdx.x * 128;

    const int mr = (warp & 3) * 32;          // warp row base
    const int nc = (warp >> 2) * 56;         // warp col base
    const int nn = (nc == 0) ? 7 : 6;        // n-tiles (cols >= 104 unused)

    __shared__ float xs[128 * CI];
    for (int i = tid; i < 128 * CI; i += 256) xs[i] = x[base * 3 + i];
    __syncthreads();

    // the 4 rows this thread touches: r0+{0,8,16,24}
    const int r0 = mr + (lane >> 2);
    float xr[4][3];
    #pragma unroll
    for (int q = 0; q < 4; q++) {
        int r = r0 + q * 8;
        xr[q][0] = xs[r * 3 + 0];
        xr[q][1] = xs[r * 3 + 1];
        xr[q][2] = xs[r * 3 + 2];
    }

    float acc[2][7][4];
    #pragma unroll
    for (int mi = 0; mi < 2; mi++)
        #pragma unroll
        for (int ni = 0; ni < 7; ni++)
            #pragma unroll
            for (int q = 0; q < 4; q++) acc[mi][ni][q] = 0.0f;

    const int kc0 = lane & 3;
    const int bcol = nc + (lane >> 2);       // B fragment col base (+8*ni)

    #pragma unroll
    for (int kb = 0; kb < 8; kb++) {
        const int c_lo = kb * 8 + kc0;
        const int c_hi = c_lo + 4;

        // conv for the two A columns, 4 rows each
        float wl0 = __ldg(&Wc[c_lo]),      wl1 = __ldg(&Wc[CH + c_lo]),
              wl2 = __ldg(&Wc[2 * CH + c_lo]), bclo = __ldg(&bc[c_lo]);
        float wh0 = __ldg(&Wc[c_hi]),      wh1 = __ldg(&Wc[CH + c_hi]),
              wh2 = __ldg(&Wc[2 * CH + c_hi]), bchi = __ldg(&bc[c_hi]);

        uint32_t a[2][4];
        #pragma unroll
        for (int mi = 0; mi < 2; mi++) {
            #pragma unroll
            for (int h = 0; h < 2; h++) {       // row r0 + mi*16 + h*8
                int q = mi * 2 + h;
                float lo = bclo + xr[q][0] * wl0 + xr[q][1] * wl1 + xr[q][2] * wl2;
                float hi = bchi + xr[q][0] * wh0 + xr[q][1] * wh1 + xr[q][2] * wh2;
                a[mi][h]     = to_tf32(fmaxf(lo, 0.0f));
                a[mi][h + 2] = to_tf32(fmaxf(hi, 0.0f));
            }
        }

        #pragma unroll
        for (int ni = 0; ni < 7; ni++) {
            if (ni >= nn) break;
            int col = bcol + ni * 8;
            int cl = (col > 99) ? 99 : col;   // clamp padded cols (discarded)
            uint32_t b[2];
            b[0] = __float_as_uint(to_tf32(__ldg(&Wl[c_lo * G4 + cl])) * 0 + 0) ; // placeholder
            // real loads:
            b[0] = to_tf32(__ldg(&Wl[c_lo * G4 + cl]));
            b[1] = to_tf32(__ldg(&Wl[c_hi * G4 + cl]));
            mma_tf32(acc[0][ni], a[0], b);
            mma_tf32(acc[1][ni], a[1], b);
        }
    }

    // epilogue: add bl, scatter to g_zx[n][v][t][g]
    #pragma unroll
    for (int mi = 0; mi < 2; mi++) {
        #pragma unroll
        for (int h = 0; h < 2; h++) {
            size_t row = base + r0 + mi * 16 + h * 8;
            int nt = (int)(row / VV);
            int v  = (int)(row - (size_t)nt * VV);
            int n  = nt >> 9, t = nt & 511;
            float* dst = &g_zx[(((size_t)n * VV + v) * TT + t) * G4];
            #pragma unroll
            for (int ni = 0; ni < 7; ni++) {
                if (ni >= nn) break;
                int cc = nc + ni * 8 + 2 * (lane & 3);
                if (cc < 100) {
                    float2 o;
                    o.x = acc[mi][ni][2 * h + 0] + __ldg(&bl[cc]);
                    o.y = acc[mi][ni][2 * h + 1] + __ldg(&bl[cc + 1]);
                    *reinterpret_cast<float2*>(dst + cc) = o;
                }
            }
        }
    }
}

// ---------------------------------------------------------------------------
// Kernel B: warp-per-(n,v) LSTM scan. U in registers, h via shfl.
// Depth-8 register prefetch ring to hide DRAM latency.
// ---------------------------------------------------------------------------
__global__ void __launch_bounds__(64) lstm_kernel(
    const float* __restrict__ U)   // (FF, G4)
{
    const int lane = threadIdx.x & 31;
    const int warp = threadIdx.x >> 5;
    const int nv = blockIdx.x * 2 + warp;
    const int n = nv / VV, v = nv % VV;
    const int j = (lane < FF) ? lane : 0;
    const bool act = (lane < FF);

    ull u_if[FF], u_go[FF];
    #pragma unroll
    for (int f = 0; f < FF; f++) {
        u_if[f] = pack2(U[f * G4 + j],          U[f * G4 + FF + j]);
        u_go[f] = pack2(U[f * G4 + 2 * FF + j], U[f * G4 + 3 * FF + j]);
    }

    const float* zp = g_zx + (size_t)nv * TT * G4;
    float* f1p = g_f1 + ((size_t)n * TT) * (VV * FF) + (size_t)v * FF + j;

    float h = 0.0f, c = 0.0f;

    float zbuf[8][4];
    #pragma unroll
    for (int i = 0; i < 8; i++) {
        const float* q = zp + (size_t)i * G4;
        zbuf[i][0] = q[j];          zbuf[i][1] = q[FF + j];
        zbuf[i][2] = q[2 * FF + j]; zbuf[i][3] = q[3 * FF + j];
    }

    for (int tb = 0; tb < TT; tb += 8) {
        #pragma unroll
        for (int i = 0; i < 8; i++) {
            const int t = tb + i;
            float z0 = zbuf[i][0], z1 = zbuf[i][1], z2 = zbuf[i][2], z3 = zbuf[i][3];

            if (t + 8 < TT) {
                const float* q = zp + (size_t)(t + 8) * G4;
                zbuf[i][0] = q[j];          zbuf[i][1] = q[FF + j];
                zbuf[i][2] = q[2 * FF + j]; zbuf[i][3] = q[3 * FF + j];
            }

            ull if0 = pack2(z0, z1), if1 = 0;
            ull go0 = pack2(z2, z3), go1 = 0;
            #pragma unroll
            for (int f = 0; f < 12; f++) {
                float hb = __shfl_sync(0xffffffffu, h, f);
                ull hh = pack2(hb, hb);
                if0 = fma2(hh, u_if[f], if0);
                go0 = fma2(hh, u_go[f], go0);
            }
            #pragma unroll
            for (int f = 12; f < FF; f++) {
                float hb = __shfl_sync(0xffffffffu, h, f);
                ull hh = pack2(hb, hb);
                if1 = fma2(hh, u_if[f], if1);
                go1 = fma2(hh, u_go[f], go1);
            }
            ull acc_if = add2(if0, if1);
            ull acc_go = add2(go0, go1);

            float gi, gf, gg, go;
            unpack2(acc_if, gi, gf);
            unpack2(acc_go, gg, go);
            c = hsig(gf) * c + hsig(gi) * tanh_hw(gg);
            h = hsig(go) * tanh_hw(c);
            if (act) f1p[(size_t)t * (VV * FF)] = h;
        }
    }
}

// ---------------------------------------------------------------------------
// Kernel C: coefs = softmax(leaky_relu(f1)+bias); out = coefs @ x1
// ---------------------------------------------------------------------------
__global__ void __launch_bounds__(256) attn_kernel(
    const float* __restrict__ x,
    const float* __restrict__ Wc,
    const float* __restrict__ bc,
    const float* __restrict__ bias,
    float* __restrict__ out)
{
    const int nt = blockIdx.x;
    const int tid = threadIdx.x;

    __shared__ float xs[VV * CI];
    __shared__ __align__(16) float x1s[VV * 72];
    __shared__ float ft[VV * FF];
    __shared__ float cfs[VV][FF];

    if (tid < VV * CI) xs[tid] = x[(size_t)nt * (VV * CI) + tid];
    for (int i = tid; i < VV * FF; i += 256)
        ft[i] = g_f1[(size_t)nt * (VV * FF) + i];
    __syncthreads();

    for (int i = tid; i < VV * CH; i += 256) {
        int v = i >> 6, d = i & 63;
        float a = bc[d];
        a += xs[v * 3 + 0] * Wc[0 * CH + d];
        a += xs[v * 3 + 1] * Wc[1 * CH + d];
        a += xs[v * 3 + 2] * Wc[2 * CH + d];
        x1s[v * 72 + d] = fmaxf(a, 0.0f);
    }

    if (tid < VV) {
        float e[FF];
        float mx = -1e30f;
        #pragma unroll
        for (int w = 0; w < FF; w++) {
            float f = ft[tid * FF + w];
            f = (f > 0.0f) ? f : 0.2f * f;
            f += bias[tid * VV + w];
            e[w] = f;
            mx = fmaxf(mx, f);
        }
        float s = 0.0f;
        #pragma unroll
        for (int w = 0; w < FF; w++) { float ev = __expf(e[w] - mx); e[w] = ev; s += ev; }
        float inv = __fdividef(1.0f, s);
        #pragma unroll
        for (int w = 0; w < FF; w++) cfs[tid][w] = e[w] * inv;
    }
    __syncthreads();

    if (tid < 200) {
        const int v = tid >> 3;
        const int d8 = (tid & 7) * 8;
        ull a0 = 0, a1 = 0, a2 = 0, a3 = 0;
        #pragma unroll
        for (int w = 0; w < FF; w++) {
            float cv = cfs[v][w];
            ull cc = pack2(cv, cv);
            const float4* r = reinterpret_cast<const float4*>(&x1s[w * 72 + d8]);
            float4 A = r[0], B = r[1];
            a0 = fma2(cc, pack2(A.x, A.y), a0);
            a1 = fma2(cc, pack2(A.z, A.w), a1);
            a2 = fma2(cc, pack2(B.x, B.y), a2);
            a3 = fma2(cc, pack2(B.z, B.w), a3);
        }
        float4 r0, r1;
        unpack2(a0, r0.x, r0.y); unpack2(a1, r0.z, r0.w);
        unpack2(a2, r1.x, r1.y); unpack2(a3, r1.z, r1.w);
        float4* o = reinterpret_cast<float4*>(out + (size_t)nt * (VV * CH) + v * CH + d8);
        o[0] = r0; o[1] = r1;
    }
}

// ---------------------------------------------------------------------------
extern "C" void kernel_launch(void* const* d_in, const int* in_sizes, int n_in,
                              void* d_out, int out_size) {
    const float* x    = (const float*)d_in[0];
    const float* Wc   = (const float*)d_in[1];
    const float* bc   = (const float*)d_in[2];
    const float* Wl   = (const float*)d_in[3];
    const float* U    = (const float*)d_in[4];
    const float* bl   = (const float*)d_in[5];
    const float* bias = (const float*)d_in[6];
    float* out = (float*)d_out;

    zx_kernel<<<(int)(MROWS / 128), 256>>>(x, Wc, bc, Wl, bl);
    lstm_kernel<<<NN * VV / 2, 64>>>(U);
    attn_kernel<<<NN * TT, 256>>>(x, Wc, bc, bias, out);
}

// round 11
// speedup vs baseline: 4.2479x; 1.6030x over previous
#include <cuda_runtime.h>
#include <cstdint>

#define NN 64
#define TT 512
#define VV 25
#define CI 3
#define CH 64
#define FF 25
#define G4 100   // 4*FF
#define MROWS ((size_t)NN * TT * VV)   // 819200
#define F1P 640  // padded f1 row stride (floats) per (n,t)

// Scratch (device globals: allocation-free per harness rules)
__device__ float g_zx[(size_t)NN * VV * TT * G4];   // [n][v][t][g]
__device__ float g_f1[(size_t)NN * TT * F1P];       // [n][t][v*25+f], padded

typedef unsigned long long ull;

__device__ __forceinline__ ull pack2(float a, float b) {
    ull r;
    asm("mov.b64 %0, {%1,%2};" : "=l"(r) : "r"(__float_as_uint(a)), "r"(__float_as_uint(b)));
    return r;
}
__device__ __forceinline__ void unpack2(ull p, float& a, float& b) {
    unsigned int x, y;
    asm("mov.b64 {%0,%1}, %2;" : "=r"(x), "=r"(y) : "l"(p));
    a = __uint_as_float(x); b = __uint_as_float(y);
}
__device__ __forceinline__ ull fma2(ull a, ull b, ull c) {
    ull d;
    asm("fma.rn.f32x2 %0, %1, %2, %3;" : "=l"(d) : "l"(a), "l"(b), "l"(c));
    return d;
}
__device__ __forceinline__ ull add2(ull a, ull b) {
    ull d;
    asm("add.rn.f32x2 %0, %1, %2;" : "=l"(d) : "l"(a), "l"(b));
    return d;
}
__device__ __forceinline__ float hsig(float x) {
    return fminf(fmaxf(0.2f * x + 0.5f, 0.0f), 1.0f);
}
__device__ __forceinline__ float tanh_hw(float x) {
    float y;
    asm("tanh.approx.f32 %0, %1;" : "=f"(y) : "f"(x));
    return y;
}
__device__ __forceinline__ uint32_t to_tf32(float x) {
    uint32_t r;
    asm("cvt.rna.tf32.f32 %0, %1;" : "=r"(r) : "f"(x));
    return r;
}
__device__ __forceinline__ void mma_tf32(float* c, const uint32_t* a, const uint32_t* b) {
    asm("mma.sync.aligned.m16n8k8.row.col.f32.tf32.tf32.f32 "
        "{%0,%1,%2,%3}, {%4,%5,%6,%7}, {%8,%9}, {%0,%1,%2,%3};"
        : "+f"(c[0]), "+f"(c[1]), "+f"(c[2]), "+f"(c[3])
        : "r"(a[0]), "r"(a[1]), "r"(a[2]), "r"(a[3]), "r"(b[0]), "r"(b[1]));
}

// ---------------------------------------------------------------------------
// Kernel A: tf32 mma.sync GEMM.  zx[row,:] = relu(x[row]@Wc+bc) @ Wl + bl
// (R6-passing version, 162us)
// ---------------------------------------------------------------------------
__global__ void __launch_bounds__(256) zx_kernel(
    const float* __restrict__ x,
    const float* __restrict__ Wc,
    const float* __restrict__ bc,
    const float* __restrict__ Wl,
    const float* __restrict__ bl)
{
    const int tid  = threadIdx.x;
    const int warp = tid >> 5;
    const int lane = tid & 31;
    const size_t base = (size_t)blockIdx.x * 128;

    const int mr = (warp & 3) * 32;
    const int nc = (warp >> 2) * 56;
    const int nn = (nc == 0) ? 7 : 6;

    __shared__ float xs[128 * CI];
    for (int i = tid; i < 128 * CI; i += 256) xs[i] = x[base * 3 + i];
    __syncthreads();

    const int r0 = mr + (lane >> 2);
    float xr[4][3];
    #pragma unroll
    for (int q = 0; q < 4; q++) {
        int r = r0 + q * 8;
        xr[q][0] = xs[r * 3 + 0];
        xr[q][1] = xs[r * 3 + 1];
        xr[q][2] = xs[r * 3 + 2];
    }

    float acc[2][7][4];
    #pragma unroll
    for (int mi = 0; mi < 2; mi++)
        #pragma unroll
        for (int ni = 0; ni < 7; ni++)
            #pragma unroll
            for (int q = 0; q < 4; q++) acc[mi][ni][q] = 0.0f;

    const int kc0 = lane & 3;
    const int bcol = nc + (lane >> 2);

    #pragma unroll
    for (int kb = 0; kb < 8; kb++) {
        const int c_lo = kb * 8 + kc0;
        const int c_hi = c_lo + 4;

        float wl0 = __ldg(&Wc[c_lo]),      wl1 = __ldg(&Wc[CH + c_lo]),
              wl2 = __ldg(&Wc[2 * CH + c_lo]), bclo = __ldg(&bc[c_lo]);
        float wh0 = __ldg(&Wc[c_hi]),      wh1 = __ldg(&Wc[CH + c_hi]),
              wh2 = __ldg(&Wc[2 * CH + c_hi]), bchi = __ldg(&bc[c_hi]);

        uint32_t a[2][4];
        #pragma unroll
        for (int mi = 0; mi < 2; mi++) {
            #pragma unroll
            for (int h = 0; h < 2; h++) {
                int q = mi * 2 + h;
                float lo = bclo + xr[q][0] * wl0 + xr[q][1] * wl1 + xr[q][2] * wl2;
                float hi = bchi + xr[q][0] * wh0 + xr[q][1] * wh1 + xr[q][2] * wh2;
                a[mi][h]     = to_tf32(fmaxf(lo, 0.0f));
                a[mi][h + 2] = to_tf32(fmaxf(hi, 0.0f));
            }
        }

        #pragma unroll
        for (int ni = 0; ni < 7; ni++) {
            if (ni >= nn) break;
            int col = bcol + ni * 8;
            int cl = (col > 99) ? 99 : col;
            uint32_t b[2];
            b[0] = to_tf32(__ldg(&Wl[c_lo * G4 + cl]));
            b[1] = to_tf32(__ldg(&Wl[c_hi * G4 + cl]));
            mma_tf32(acc[0][ni], a[0], b);
            mma_tf32(acc[1][ni], a[1], b);
        }
    }

    #pragma unroll
    for (int mi = 0; mi < 2; mi++) {
        #pragma unroll
        for (int h = 0; h < 2; h++) {
            size_t row = base + r0 + mi * 16 + h * 8;
            int nt = (int)(row / VV);
            int v  = (int)(row - (size_t)nt * VV);
            int n  = nt >> 9, t = nt & 511;
            float* dst = &g_zx[(((size_t)n * VV + v) * TT + t) * G4];
            #pragma unroll
            for (int ni = 0; ni < 7; ni++) {
                if (ni >= nn) break;
                int cc = nc + ni * 8 + 2 * (lane & 3);
                if (cc < 100) {
                    float2 o;
                    o.x = acc[mi][ni][2 * h + 0] + __ldg(&bl[cc]);
                    o.y = acc[mi][ni][2 * h + 1] + __ldg(&bl[cc + 1]);
                    *reinterpret_cast<float2*>(dst + cc) = o;
                }
            }
        }
    }
}

// ---------------------------------------------------------------------------
// Kernel B: warp-per-(n,v) LSTM scan (R6-passing, padded f1 layout).
// ---------------------------------------------------------------------------
__global__ void __launch_bounds__(64) lstm_kernel(
    const float* __restrict__ U)
{
    const int lane = threadIdx.x & 31;
    const int warp = threadIdx.x >> 5;
    const int nv = blockIdx.x * 2 + warp;
    const int n = nv / VV, v = nv % VV;
    const int j = (lane < FF) ? lane : 0;
    const bool act = (lane < FF);

    ull u_if[FF], u_go[FF];
    #pragma unroll
    for (int f = 0; f < FF; f++) {
        u_if[f] = pack2(U[f * G4 + j],          U[f * G4 + FF + j]);
        u_go[f] = pack2(U[f * G4 + 2 * FF + j], U[f * G4 + 3 * FF + j]);
    }

    const float* zp = g_zx + (size_t)nv * TT * G4;
    float* f1p = g_f1 + ((size_t)n * TT) * F1P + (size_t)v * FF + j;

    float h = 0.0f, c = 0.0f;

    float zbuf[8][4];
    #pragma unroll
    for (int i = 0; i < 8; i++) {
        const float* q = zp + (size_t)i * G4;
        zbuf[i][0] = q[j];          zbuf[i][1] = q[FF + j];
        zbuf[i][2] = q[2 * FF + j]; zbuf[i][3] = q[3 * FF + j];
    }

    for (int tb = 0; tb < TT; tb += 8) {
        #pragma unroll
        for (int i = 0; i < 8; i++) {
            const int t = tb + i;
            float z0 = zbuf[i][0], z1 = zbuf[i][1], z2 = zbuf[i][2], z3 = zbuf[i][3];

            if (t + 8 < TT) {
                const float* q = zp + (size_t)(t + 8) * G4;
                zbuf[i][0] = q[j];          zbuf[i][1] = q[FF + j];
                zbuf[i][2] = q[2 * FF + j]; zbuf[i][3] = q[3 * FF + j];
            }

            ull if0 = pack2(z0, z1), if1 = 0;
            ull go0 = pack2(z2, z3), go1 = 0;
            #pragma unroll
            for (int f = 0; f < 12; f++) {
                float hb = __shfl_sync(0xffffffffu, h, f);
                ull hh = pack2(hb, hb);
                if0 = fma2(hh, u_if[f], if0);
                go0 = fma2(hh, u_go[f], go0);
            }
            #pragma unroll
            for (int f = 12; f < FF; f++) {
                float hb = __shfl_sync(0xffffffffu, h, f);
                ull hh = pack2(hb, hb);
                if1 = fma2(hh, u_if[f], if1);
                go1 = fma2(hh, u_go[f], go1);
            }
            ull acc_if = add2(if0, if1);
            ull acc_go = add2(go0, go1);

            float gi, gf, gg, go;
            unpack2(acc_if, gi, gf);
            unpack2(acc_go, gg, go);
            c = hsig(gf) * c + hsig(gi) * tanh_hw(gg);
            h = hsig(go) * tanh_hw(c);
            if (act) f1p[(size_t)t * F1P] = h;
        }
    }
}

// ---------------------------------------------------------------------------
// Kernel C: tensor-core attention.  One warp per (n,t) tile, 4 warps/block.
// softmax rows lane-parallel; out = coefs @ x1 via mma.sync tf32, with the
// x1 B-fragments built in-register straight from the 3-channel conv.
// ---------------------------------------------------------------------------
__global__ void __launch_bounds__(128) attn_kernel(
    const float* __restrict__ x,
    const float* __restrict__ Wc,
    const float* __restrict__ bc,
    const float* __restrict__ bias,
    float* __restrict__ out)
{
    const int tid = threadIdx.x;
    const int warp = tid >> 5, lane = tid & 31;
    const int nt = blockIdx.x * 4 + warp;

    __shared__ float Wcs[CI * CH];
    __shared__ float bcs[CH];
    __shared__ __align__(16) float f1s[4][F1P];
    __shared__ float xss[4][76];
    __shared__ float cfs[4][32][36];

    for (int i = tid; i < CI * CH; i += 128) Wcs[i] = Wc[i];
    if (tid < CH) bcs[tid] = bc[tid];

    // per-warp stage f1 (padded 640 floats, 16B-aligned) and x (75 floats)
    {
        const float4* src = reinterpret_cast<const float4*>(g_f1 + (size_t)nt * F1P);
        float4* dst = reinterpret_cast<float4*>(f1s[warp]);
        for (int i = lane; i < F1P / 4; i += 32) dst[i] = src[i];
        for (int i = lane; i < VV * CI; i += 32) xss[warp][i] = x[(size_t)nt * (VV * CI) + i];
    }
    __syncthreads();

    // softmax(leaky_relu(f1)+bias) — lane v owns row v
    if (lane < VV) {
        float e[FF];
        float mx = -1e30f;
        const float* fr = &f1s[warp][lane * FF];
        const float* br = bias + lane * VV;
        #pragma unroll
        for (int w = 0; w < FF; w++) {
            float f = fr[w];
            f = (f > 0.0f) ? f : 0.2f * f;
            f += __ldg(&br[w]);
            e[w] = f;
            mx = fmaxf(mx, f);
        }
        float s = 0.0f;
        #pragma unroll
        for (int w = 0; w < FF; w++) { e[w] = __expf(e[w] - mx); s += e[w]; }
        float inv = __fdividef(1.0f, s);
        #pragma unroll
        for (int w = 0; w < FF; w++)
            cfs[warp][lane][w] = __uint_as_float(to_tf32(e[w] * inv));
        #pragma unroll
        for (int w = FF; w < 32; w++) cfs[warp][lane][w] = 0.0f;   // zero k-pad
    }
    __syncwarp();

    // A fragments: coefs (m=v rows, k=w cols), 2 m-tiles x 4 k-tiles
    const int g = lane >> 2, kq = lane & 3;
    uint32_t af[2][4][4];
    #pragma unroll
    for (int mi = 0; mi < 2; mi++)
        #pragma unroll
        for (int ki = 0; ki < 4; ki++) {
            af[mi][ki][0] = __float_as_uint(cfs[warp][16 * mi + g    ][8 * ki + kq]);
            af[mi][ki][1] = __float_as_uint(cfs[warp][16 * mi + g + 8][8 * ki + kq]);
            af[mi][ki][2] = __float_as_uint(cfs[warp][16 * mi + g    ][8 * ki + kq + 4]);
            af[mi][ki][3] = __float_as_uint(cfs[warp][16 * mi + g + 8][8 * ki + kq + 4]);
        }

    // x rows this lane needs for B fragments: w = kq + 4*jj
    float xw0[8], xw1[8], xw2[8];
    bool wok[8];
    #pragma unroll
    for (int jj = 0; jj < 8; jj++) {
        int w = kq + 4 * jj;
        int wc = (w < VV) ? w : 0;
        xw0[jj] = xss[warp][wc * 3 + 0];
        xw1[jj] = xss[warp][wc * 3 + 1];
        xw2[jj] = xss[warp][wc * 3 + 2];
        wok[jj] = (w < VV);
    }

    float* obase = out + (size_t)nt * (VV * CH);

    #pragma unroll
    for (int ni = 0; ni < 8; ni++) {
        const int d = 8 * ni + g;
        const float w0 = Wcs[d], w1 = Wcs[CH + d], w2 = Wcs[2 * CH + d], bd = bcs[d];

        float acc0[4] = {0.f, 0.f, 0.f, 0.f};
        float acc1[4] = {0.f, 0.f, 0.f, 0.f};

        #pragma unroll
        for (int ki = 0; ki < 4; ki++) {
            float v0 = bd + xw0[2 * ki] * w0 + xw1[2 * ki] * w1 + xw2[2 * ki] * w2;
            float v1 = bd + xw0[2 * ki + 1] * w0 + xw1[2 * ki + 1] * w1 + xw2[2 * ki + 1] * w2;
            v0 = wok[2 * ki]     ? fmaxf(v0, 0.0f) : 0.0f;
            v1 = wok[2 * ki + 1] ? fmaxf(v1, 0.0f) : 0.0f;
            uint32_t b[2];
            b[0] = to_tf32(v0);
            b[1] = to_tf32(v1);
            mma_tf32(acc0, af[0][ki], b);
            mma_tf32(acc1, af[1][ki], b);
        }

        const int col = 8 * ni + 2 * kq;
        *reinterpret_cast<float2*>(obase + (size_t)(g)      * CH + col) = make_float2(acc0[0], acc0[1]);
        *reinterpret_cast<float2*>(obase + (size_t)(g + 8)  * CH + col) = make_float2(acc0[2], acc0[3]);
        *reinterpret_cast<float2*>(obase + (size_t)(g + 16) * CH + col) = make_float2(acc1[0], acc1[1]);
        if (g == 0)
            *reinterpret_cast<float2*>(obase + (size_t)24 * CH + col)   = make_float2(acc1[2], acc1[3]);
    }
}

// ---------------------------------------------------------------------------
extern "C" void kernel_launch(void* const* d_in, const int* in_sizes, int n_in,
                              void* d_out, int out_size) {
    const float* x    = (const float*)d_in[0];
    const float* Wc   = (const float*)d_in[1];
    const float* bc   = (const float*)d_in[2];
    const float* Wl   = (const float*)d_in[3];
    const float* U    = (const float*)d_in[4];
    const float* bl   = (const float*)d_in[5];
    const float* bias = (const float*)d_in[6];
    float* out = (float*)d_out;

    zx_kernel<<<(int)(MROWS / 128), 256>>>(x, Wc, bc, Wl, bl);
    lstm_kernel<<<NN * VV / 2, 64>>>(U);
    attn_kernel<<<NN * TT / 4, 128>>>(x, Wc, bc, bias, out);
}